// round 9
// baseline (speedup 1.0000x reference)
#include <cuda_runtime.h>
#include <cuda_bf16.h>
#include <stdint.h>

#define N_EXPERTS 20
#define DIM 32
#define MAXB (1 << 17)     // 131072
#define TPB_B 256
#define TILE 128           // tokens per compute CTA
#define CTPB 128
#define ASTR 72            // tile row stride in bf16 elems (144B, conflict-free)

__device__ int g_cnt[N_EXPERTS];
__device__ int g_bucket[N_EXPERTS * MAXB];

// ---- kernel 1: fused bucket (warp-aggregated hist + claim + write) ------
__global__ void __launch_bounds__(TPB_B) k_bucket(const void* __restrict__ pos, int B) {
    __shared__ int sh[N_EXPERTS];
    __shared__ int sbase[N_EXPERTS];
    __shared__ int s_is64;

    if (threadIdx.x < N_EXPERTS) sh[threadIdx.x] = 0;
    if (threadIdx.x < 32) {
        // int64 pos => all odd 32-bit words are zero high-words (values < 20)
        int v = ((const int*)pos)[2 * threadIdx.x + 1];   // B >= 64 guaranteed
        unsigned nz = __ballot_sync(0xffffffffu, v != 0);
        if (threadIdx.x == 0) s_is64 = (nz == 0) ? 1 : 0;
    }
    __syncthreads();

    int t = blockIdx.x * TPB_B + threadIdx.x;
    bool valid = (t < B);
    int e = valid
          ? (s_is64 ? (int)((const long long*)pos)[t] : ((const int*)pos)[t])
          : -1;

    unsigned mm = __match_any_sync(0xffffffffu, e);
    int lane = threadIdx.x & 31;
    int rank = __popc(mm & ((1u << lane) - 1));
    int leader = __ffs(mm) - 1;
    int wbase = 0;
    if (lane == leader && valid) wbase = atomicAdd(&sh[e], __popc(mm));
    wbase = __shfl_sync(0xffffffffu, wbase, leader);
    int r = wbase + rank;

    __syncthreads();
    if (threadIdx.x < N_EXPERTS) {
        int c = sh[threadIdx.x];
        sbase[threadIdx.x] = c ? atomicAdd(&g_cnt[threadIdx.x], c) : 0;
    }
    __syncthreads();
    if (valid) g_bucket[e * MAXB + sbase[e] + r] = t;
}

// ---- mma.sync wrapper ----------------------------------------------------
__device__ __forceinline__ void mma16816(float* c, const uint32_t* a, const uint32_t* b) {
    asm volatile(
        "mma.sync.aligned.m16n8k16.row.col.f32.bf16.bf16.f32 "
        "{%0,%1,%2,%3}, {%4,%5,%6,%7}, {%8,%9}, {%0,%1,%2,%3};"
        : "+f"(c[0]), "+f"(c[1]), "+f"(c[2]), "+f"(c[3])
        : "r"(a[0]), "r"(a[1]), "r"(a[2]), "r"(a[3]), "r"(b[0]), "r"(b[1]));
}

// split one fp32 pair into hi/lo bf16
__device__ __forceinline__ void split2(float a, float b, uint32_t& hi, uint32_t& lo) {
    __nv_bfloat162 hp = __floats2bfloat162_rn(a, b);
    float ra = a - __bfloat162float(hp.x);
    float rb = b - __bfloat162float(hp.y);
    __nv_bfloat162 lp = __floats2bfloat162_rn(ra, rb);
    hi = *reinterpret_cast<uint32_t*>(&hp);
    lo = *reinterpret_cast<uint32_t*>(&lp);
}

// ---- kernel 2: HMMA compute ---------------------------------------------
// Per CTA: 128 tokens, one expert. A tile [128][72] bf16: cols 0..31 = hi(x),
// 32..63 = lo(x). W tiles [32 o][72] bf16: cols 0..31 = hi(W[o][k]), 32..63 = lo.
// Layer = A @ W^T via 6 m16n8k16 HMMA per (mtile,ntile). Warp w owns rows
// 32w..32w+31 -> writes its own A rows; one block-wide sync after staging.
// Block -> (expert, tile) map is a parallel warp-scan (one LDG latency),
// not a 20-iteration dependent-load walk.
__global__ void __launch_bounds__(CTPB) k_compute(
    const float* __restrict__ x,
    const float* __restrict__ W1, const float* __restrict__ b1,
    const float* __restrict__ W0, const float* __restrict__ b0,
    float* __restrict__ out)
{
    __shared__ __align__(16) __nv_bfloat16 sA[TILE * ASTR];      // 18432 B
    __shared__ __align__(16) __nv_bfloat16 sB1[DIM * ASTR];      // 4608 B
    __shared__ __align__(16) __nv_bfloat16 sB2[DIM * ASTR];      // 4608 B
    __shared__ __align__(16) float sb1[DIM], sb0[DIM];
    __shared__ int sTok[TILE];

    int tid = threadIdx.x;
    int l   = tid & 31;

    // ---- block -> (expert, tile): parallel load + warp scan ----
    int rem = blockIdx.x;
    int cnt = (l < N_EXPERTS) ? g_cnt[l] : 0;          // one broadcast LDG
    int nb  = (cnt + TILE - 1) / TILE;
    int s = nb;
    #pragma unroll
    for (int d = 1; d < 32; d <<= 1) {
        int u = __shfl_up_sync(0xffffffffu, s, d);
        if (l >= d) s += u;
    }
    int excl = s - nb;                                  // exclusive prefix of nb
    bool hit = (l < N_EXPERTS) && (rem >= excl) && (rem < excl + nb);
    unsigned hm = __ballot_sync(0xffffffffu, hit);
    if (hm == 0) return;                                // beyond total work (uniform)
    int el  = __ffs(hm) - 1;
    int e   = el;
    int n   = __shfl_sync(0xffffffffu, cnt, el);
    int base = (rem - __shfl_sync(0xffffffffu, excl, el)) * TILE;

    // ---- stage weights (hi/lo split) + biases ----
    #pragma unroll 1
    for (int i = tid; i < DIM * DIM; i += CTPB) {
        int o = i >> 5, k = i & 31;
        float w1v = W1[e * DIM * DIM + i];
        __nv_bfloat16 h1 = __float2bfloat16(w1v);
        sB1[o * ASTR + k]      = h1;
        sB1[o * ASTR + 32 + k] = __float2bfloat16(w1v - __bfloat162float(h1));
        float w0v = W0[e * DIM * DIM + i];
        __nv_bfloat16 h0 = __float2bfloat16(w0v);
        sB2[o * ASTR + k]      = h0;
        sB2[o * ASTR + 32 + k] = __float2bfloat16(w0v - __bfloat162float(h0));
    }
    if (tid < DIM) {
        sb1[tid] = b1[e * DIM + tid];
        sb0[tid] = b0[e * DIM + tid];
    }

    // ---- gather token row, split hi/lo into A tile ----
    int slot = base + tid;
    int tok = (slot < n) ? g_bucket[e * MAXB + slot] : -1;
    sTok[tid] = tok;
    {
        float v[DIM];
        #pragma unroll
        for (int j = 0; j < DIM; j++) v[j] = 0.0f;
        if (tok >= 0) {
            const float4* xp = (const float4*)(x + (size_t)tok * DIM);
            #pragma unroll
            for (int j = 0; j < DIM / 4; j++) {
                float4 q = xp[j];
                v[4*j+0] = q.x; v[4*j+1] = q.y; v[4*j+2] = q.z; v[4*j+3] = q.w;
            }
        }
        uint32_t rw[32];
        #pragma unroll
        for (int j = 0; j < 16; j++) split2(v[2*j], v[2*j+1], rw[j], rw[16 + j]);
        uint4* rp = (uint4*)(sA + tid * ASTR);
        #pragma unroll
        for (int q = 0; q < 8; q++)
            rp[q] = make_uint4(rw[4*q], rw[4*q+1], rw[4*q+2], rw[4*q+3]);
    }
    __syncthreads();

    // ---- fragment geometry ----
    int w  = tid >> 5;
    int g  = l >> 2;           // 0..7
    int t4 = l & 3;            // 0..3
    const int kA[6] = {0, 16, 32, 48, 0, 16};
    const int kB[6] = {0, 16, 0, 16, 32, 48};

    float acc[2][4][4];

    // ======================= layer 1 =======================
    #pragma unroll
    for (int mt = 0; mt < 2; mt++)
        #pragma unroll
        for (int nt = 0; nt < 4; nt++) {
            float2 bv = *(const float2*)&sb1[nt * 8 + 2 * t4];
            acc[mt][nt][0] = bv.x; acc[mt][nt][1] = bv.y;
            acc[mt][nt][2] = bv.x; acc[mt][nt][3] = bv.y;
        }
    #pragma unroll
    for (int ks = 0; ks < 6; ks++) {
        uint32_t bf[4][2];
        #pragma unroll
        for (int nt = 0; nt < 4; nt++) {
            bf[nt][0] = *(const uint32_t*)&sB1[(nt * 8 + g) * ASTR + kB[ks] + 2 * t4];
            bf[nt][1] = *(const uint32_t*)&sB1[(nt * 8 + g) * ASTR + kB[ks] + 2 * t4 + 8];
        }
        #pragma unroll
        for (int mt = 0; mt < 2; mt++) {
            int r0 = w * 32 + mt * 16 + g;
            uint32_t af[4];
            af[0] = *(const uint32_t*)&sA[r0       * ASTR + kA[ks] + 2 * t4];
            af[1] = *(const uint32_t*)&sA[(r0 + 8) * ASTR + kA[ks] + 2 * t4];
            af[2] = *(const uint32_t*)&sA[r0       * ASTR + kA[ks] + 2 * t4 + 8];
            af[3] = *(const uint32_t*)&sA[(r0 + 8) * ASTR + kA[ks] + 2 * t4 + 8];
            #pragma unroll
            for (int nt = 0; nt < 4; nt++) mma16816(acc[mt][nt], af, bf[nt]);
        }
    }

    // write h back into A tile (hi/lo), own rows only
    #pragma unroll
    for (int mt = 0; mt < 2; mt++) {
        int r0 = w * 32 + mt * 16 + g;
        #pragma unroll
        for (int nt = 0; nt < 4; nt++) {
            int c = nt * 8 + 2 * t4;
            uint32_t hi0, lo0, hi1, lo1;
            split2(acc[mt][nt][0], acc[mt][nt][1], hi0, lo0);
            split2(acc[mt][nt][2], acc[mt][nt][3], hi1, lo1);
            *(uint32_t*)&sA[r0 * ASTR + c]            = hi0;
            *(uint32_t*)&sA[r0 * ASTR + 32 + c]       = lo0;
            *(uint32_t*)&sA[(r0 + 8) * ASTR + c]      = hi1;
            *(uint32_t*)&sA[(r0 + 8) * ASTR + 32 + c] = lo1;
        }
    }
    __syncwarp();

    // ======================= layer 0 =======================
    #pragma unroll
    for (int mt = 0; mt < 2; mt++)
        #pragma unroll
        for (int nt = 0; nt < 4; nt++) {
            float2 bv = *(const float2*)&sb0[nt * 8 + 2 * t4];
            acc[mt][nt][0] = bv.x; acc[mt][nt][1] = bv.y;
            acc[mt][nt][2] = bv.x; acc[mt][nt][3] = bv.y;
        }
    #pragma unroll
    for (int ks = 0; ks < 6; ks++) {
        uint32_t bf[4][2];
        #pragma unroll
        for (int nt = 0; nt < 4; nt++) {
            bf[nt][0] = *(const uint32_t*)&sB2[(nt * 8 + g) * ASTR + kB[ks] + 2 * t4];
            bf[nt][1] = *(const uint32_t*)&sB2[(nt * 8 + g) * ASTR + kB[ks] + 2 * t4 + 8];
        }
        #pragma unroll
        for (int mt = 0; mt < 2; mt++) {
            int r0 = w * 32 + mt * 16 + g;
            uint32_t af[4];
            af[0] = *(const uint32_t*)&sA[r0       * ASTR + kA[ks] + 2 * t4];
            af[1] = *(const uint32_t*)&sA[(r0 + 8) * ASTR + kA[ks] + 2 * t4];
            af[2] = *(const uint32_t*)&sA[r0       * ASTR + kA[ks] + 2 * t4 + 8];
            af[3] = *(const uint32_t*)&sA[(r0 + 8) * ASTR + kA[ks] + 2 * t4 + 8];
            #pragma unroll
            for (int nt = 0; nt < 4; nt++) mma16816(acc[mt][nt], af, bf[nt]);
        }
    }

    // ---- epilogue: row sum-of-squares (4-lane bfly), normalize, store ----
    #pragma unroll
    for (int mt = 0; mt < 2; mt++) {
        int r0 = w * 32 + mt * 16 + g;
        float s0 = 0.0f, s1 = 0.0f;
        #pragma unroll
        for (int nt = 0; nt < 4; nt++) {
            s0 = fmaf(acc[mt][nt][0], acc[mt][nt][0], s0);
            s0 = fmaf(acc[mt][nt][1], acc[mt][nt][1], s0);
            s1 = fmaf(acc[mt][nt][2], acc[mt][nt][2], s1);
            s1 = fmaf(acc[mt][nt][3], acc[mt][nt][3], s1);
        }
        s0 += __shfl_xor_sync(0xffffffffu, s0, 1);
        s0 += __shfl_xor_sync(0xffffffffu, s0, 2);
        s1 += __shfl_xor_sync(0xffffffffu, s1, 1);
        s1 += __shfl_xor_sync(0xffffffffu, s1, 2);
        float inv0 = 1.0f / fmaxf(sqrtf(s0), 1e-12f);
        float inv1 = 1.0f / fmaxf(sqrtf(s1), 1e-12f);

        int tok0 = sTok[r0];
        int tok1 = sTok[r0 + 8];
        #pragma unroll
        for (int nt = 0; nt < 4; nt++) {
            int c = nt * 8 + 2 * t4;
            if (tok0 >= 0) {
                float2 v = make_float2(acc[mt][nt][0] * inv0, acc[mt][nt][1] * inv0);
                *(float2*)(out + (size_t)tok0 * DIM + c) = v;
            }
            if (tok1 >= 0) {
                float2 v = make_float2(acc[mt][nt][2] * inv1, acc[mt][nt][3] * inv1);
                *(float2*)(out + (size_t)tok1 * DIM + c) = v;
            }
        }
    }
}

// ---------------- launch -------------------------------------------------
extern "C" void kernel_launch(void* const* d_in, const int* in_sizes, int n_in,
                              void* d_out, int out_size) {
    const float* x  = (const float*)d_in[0];
    const float* W1 = (const float*)d_in[1];
    const float* b1 = (const float*)d_in[2];
    const float* W0 = (const float*)d_in[3];
    const float* b0 = (const float*)d_in[4];
    const void*  pos = d_in[5];
    float* out = (float*)d_out;

    int B = in_sizes[0] / DIM;
    if (B > MAXB) B = MAXB;
    int nblk_b = (B + TPB_B - 1) / TPB_B;
    int nblk_c = (B + TILE - 1) / TILE + N_EXPERTS - 1;

    void* cnt_ptr = nullptr;
    cudaGetSymbolAddress(&cnt_ptr, g_cnt);
    cudaMemsetAsync(cnt_ptr, 0, N_EXPERTS * sizeof(int), 0);

    k_bucket<<<nblk_b, TPB_B>>>(pos, B);
    k_compute<<<nblk_c, CTPB>>>(x, W1, b1, W0, b0, out);
}

// round 10
// speedup vs baseline: 1.1004x; 1.1004x over previous
#include <cuda_runtime.h>
#include <cuda_bf16.h>
#include <stdint.h>

#define N_EXPERTS 20
#define DIM 32
#define MAXB (1 << 17)     // 131072
#define TPB_B 256
#define TILE 128           // tokens per compute CTA
#define CTPB 128
#define ASTR 72            // tile row stride in bf16 elems (144B, conflict-free)

__device__ int g_cnt[N_EXPERTS];
__device__ int g_bucket[N_EXPERTS * MAXB];

// ---- kernel 1: fused bucket (warp-aggregated hist + claim + write) ------
__global__ void __launch_bounds__(TPB_B) k_bucket(const void* __restrict__ pos, int B) {
    __shared__ int sh[N_EXPERTS];
    __shared__ int sbase[N_EXPERTS];
    __shared__ int s_is64;

    if (threadIdx.x < N_EXPERTS) sh[threadIdx.x] = 0;
    if (threadIdx.x < 32) {
        // int64 pos => all odd 32-bit words are zero high-words (values < 20)
        int v = ((const int*)pos)[2 * threadIdx.x + 1];   // B >= 64 guaranteed
        unsigned nz = __ballot_sync(0xffffffffu, v != 0);
        if (threadIdx.x == 0) s_is64 = (nz == 0) ? 1 : 0;
    }
    __syncthreads();

    int t = blockIdx.x * TPB_B + threadIdx.x;
    bool valid = (t < B);
    int e = valid
          ? (s_is64 ? (int)((const long long*)pos)[t] : ((const int*)pos)[t])
          : -1;

    unsigned mm = __match_any_sync(0xffffffffu, e);
    int lane = threadIdx.x & 31;
    int rank = __popc(mm & ((1u << lane) - 1));
    int leader = __ffs(mm) - 1;
    int wbase = 0;
    if (lane == leader && valid) wbase = atomicAdd(&sh[e], __popc(mm));
    wbase = __shfl_sync(0xffffffffu, wbase, leader);
    int r = wbase + rank;

    __syncthreads();
    if (threadIdx.x < N_EXPERTS) {
        int c = sh[threadIdx.x];
        sbase[threadIdx.x] = c ? atomicAdd(&g_cnt[threadIdx.x], c) : 0;
    }
    __syncthreads();
    if (valid) g_bucket[e * MAXB + sbase[e] + r] = t;
}

// ---- mma.sync wrapper ----------------------------------------------------
__device__ __forceinline__ void mma16816(float* c, const uint32_t* a, const uint32_t* b) {
    asm volatile(
        "mma.sync.aligned.m16n8k16.row.col.f32.bf16.bf16.f32 "
        "{%0,%1,%2,%3}, {%4,%5,%6,%7}, {%8,%9}, {%0,%1,%2,%3};"
        : "+f"(c[0]), "+f"(c[1]), "+f"(c[2]), "+f"(c[3])
        : "r"(a[0]), "r"(a[1]), "r"(a[2]), "r"(a[3]), "r"(b[0]), "r"(b[1]));
}

// split one fp32 pair into hi/lo bf16
__device__ __forceinline__ void split2(float a, float b, uint32_t& hi, uint32_t& lo) {
    __nv_bfloat162 hp = __floats2bfloat162_rn(a, b);
    float ra = a - __bfloat162float(hp.x);
    float rb = b - __bfloat162float(hp.y);
    __nv_bfloat162 lp = __floats2bfloat162_rn(ra, rb);
    hi = *reinterpret_cast<uint32_t*>(&hp);
    lo = *reinterpret_cast<uint32_t*>(&lp);
}

// ---- kernel 2: HMMA compute ---------------------------------------------
// Prologue is MLP-structured: all weight LDGs issue first (into registers),
// the dependent tok->x gather chain overlaps their latency, conversions and
// STS happen after the data lands. A tile + sTok are warp-local, so there is
// exactly ONE block barrier (publishing sB1/sB2/biases).
__global__ void __launch_bounds__(CTPB) k_compute(
    const float* __restrict__ x,
    const float* __restrict__ W1, const float* __restrict__ b1,
    const float* __restrict__ W0, const float* __restrict__ b0,
    float* __restrict__ out)
{
    __shared__ __align__(16) __nv_bfloat16 sA[TILE * ASTR];      // 18432 B
    __shared__ __align__(16) __nv_bfloat16 sB1[DIM * ASTR];      // 4608 B
    __shared__ __align__(16) __nv_bfloat16 sB2[DIM * ASTR];      // 4608 B
    __shared__ __align__(16) float sb1[DIM], sb0[DIM];
    __shared__ int sTok[TILE];

    int tid = threadIdx.x;
    int l   = tid & 31;

    // ---- block -> (expert, tile): parallel load + warp scan ----
    int rem = blockIdx.x;
    int cnt = (l < N_EXPERTS) ? g_cnt[l] : 0;          // one broadcast LDG
    int nb  = (cnt + TILE - 1) / TILE;
    int s = nb;
    #pragma unroll
    for (int d = 1; d < 32; d <<= 1) {
        int u = __shfl_up_sync(0xffffffffu, s, d);
        if (l >= d) s += u;
    }
    int excl = s - nb;
    bool hit = (l < N_EXPERTS) && (rem >= excl) && (rem < excl + nb);
    unsigned hm = __ballot_sync(0xffffffffu, hit);
    if (hm == 0) return;                                // beyond total work (uniform)
    int el  = __ffs(hm) - 1;
    int e   = el;
    int n   = __shfl_sync(0xffffffffu, cnt, el);
    int base = (rem - __shfl_sync(0xffffffffu, excl, el)) * TILE;

    // ---- phase 1: issue ALL independent LDGs (weights), then gather chain ----
    float w1r[8], w0r[8];
    #pragma unroll
    for (int q = 0; q < 8; q++) {
        int i = tid + q * CTPB;
        w1r[q] = W1[e * DIM * DIM + i];
        w0r[q] = W0[e * DIM * DIM + i];
    }
    float bv1 = 0.0f, bv0 = 0.0f;
    if (tid < DIM) {
        bv1 = b1[e * DIM + tid];
        bv0 = b0[e * DIM + tid];
    }
    int slot = base + tid;
    int tok = (slot < n) ? g_bucket[e * MAXB + slot] : -1;
    float v[DIM];
    #pragma unroll
    for (int j = 0; j < DIM; j++) v[j] = 0.0f;
    if (tok >= 0) {
        const float4* xp = (const float4*)(x + (size_t)tok * DIM);
        #pragma unroll
        for (int j = 0; j < DIM / 4; j++) {
            float4 q = xp[j];
            v[4*j+0] = q.x; v[4*j+1] = q.y; v[4*j+2] = q.z; v[4*j+3] = q.w;
        }
    }

    // ---- phase 2: convert + STS (operands have landed) ----
    #pragma unroll
    for (int q = 0; q < 8; q++) {
        int i = tid + q * CTPB;
        int o = i >> 5, k = i & 31;
        __nv_bfloat16 h1 = __float2bfloat16(w1r[q]);
        sB1[o * ASTR + k]      = h1;
        sB1[o * ASTR + 32 + k] = __float2bfloat16(w1r[q] - __bfloat162float(h1));
        __nv_bfloat16 h0 = __float2bfloat16(w0r[q]);
        sB2[o * ASTR + k]      = h0;
        sB2[o * ASTR + 32 + k] = __float2bfloat16(w0r[q] - __bfloat162float(h0));
    }
    if (tid < DIM) {
        sb1[tid] = bv1;
        sb0[tid] = bv0;
    }
    sTok[tid] = tok;
    {
        uint32_t rw[32];
        #pragma unroll
        for (int j = 0; j < 16; j++) split2(v[2*j], v[2*j+1], rw[j], rw[16 + j]);
        uint4* rp = (uint4*)(sA + tid * ASTR);
        #pragma unroll
        for (int q = 0; q < 8; q++)
            rp[q] = make_uint4(rw[4*q], rw[4*q+1], rw[4*q+2], rw[4*q+3]);
    }
    __syncthreads();   // the ONLY block barrier: publishes sB1/sB2/biases

    // ---- fragment geometry ----
    int w  = tid >> 5;
    int g  = l >> 2;           // 0..7
    int t4 = l & 3;            // 0..3
    const int kA[6] = {0, 16, 32, 48, 0, 16};
    const int kB[6] = {0, 16, 0, 16, 32, 48};

    float acc[2][4][4];

    // ======================= layer 1 =======================
    #pragma unroll
    for (int mt = 0; mt < 2; mt++)
        #pragma unroll
        for (int nt = 0; nt < 4; nt++) {
            float2 bv = *(const float2*)&sb1[nt * 8 + 2 * t4];
            acc[mt][nt][0] = bv.x; acc[mt][nt][1] = bv.y;
            acc[mt][nt][2] = bv.x; acc[mt][nt][3] = bv.y;
        }
    #pragma unroll
    for (int ks = 0; ks < 6; ks++) {
        uint32_t bf[4][2];
        #pragma unroll
        for (int nt = 0; nt < 4; nt++) {
            bf[nt][0] = *(const uint32_t*)&sB1[(nt * 8 + g) * ASTR + kB[ks] + 2 * t4];
            bf[nt][1] = *(const uint32_t*)&sB1[(nt * 8 + g) * ASTR + kB[ks] + 2 * t4 + 8];
        }
        #pragma unroll
        for (int mt = 0; mt < 2; mt++) {
            int r0 = w * 32 + mt * 16 + g;
            uint32_t af[4];
            af[0] = *(const uint32_t*)&sA[r0       * ASTR + kA[ks] + 2 * t4];
            af[1] = *(const uint32_t*)&sA[(r0 + 8) * ASTR + kA[ks] + 2 * t4];
            af[2] = *(const uint32_t*)&sA[r0       * ASTR + kA[ks] + 2 * t4 + 8];
            af[3] = *(const uint32_t*)&sA[(r0 + 8) * ASTR + kA[ks] + 2 * t4 + 8];
            #pragma unroll
            for (int nt = 0; nt < 4; nt++) mma16816(acc[mt][nt], af, bf[nt]);
        }
    }

    // write h back into A tile (hi/lo) — warp-local rows only
    #pragma unroll
    for (int mt = 0; mt < 2; mt++) {
        int r0 = w * 32 + mt * 16 + g;
        #pragma unroll
        for (int nt = 0; nt < 4; nt++) {
            int c = nt * 8 + 2 * t4;
            uint32_t hi0, lo0, hi1, lo1;
            split2(acc[mt][nt][0], acc[mt][nt][1], hi0, lo0);
            split2(acc[mt][nt][2], acc[mt][nt][3], hi1, lo1);
            *(uint32_t*)&sA[r0 * ASTR + c]            = hi0;
            *(uint32_t*)&sA[r0 * ASTR + 32 + c]       = lo0;
            *(uint32_t*)&sA[(r0 + 8) * ASTR + c]      = hi1;
            *(uint32_t*)&sA[(r0 + 8) * ASTR + 32 + c] = lo1;
        }
    }
    __syncwarp();

    // ======================= layer 0 =======================
    #pragma unroll
    for (int mt = 0; mt < 2; mt++)
        #pragma unroll
        for (int nt = 0; nt < 4; nt++) {
            float2 bv = *(const float2*)&sb0[nt * 8 + 2 * t4];
            acc[mt][nt][0] = bv.x; acc[mt][nt][1] = bv.y;
            acc[mt][nt][2] = bv.x; acc[mt][nt][3] = bv.y;
        }
    #pragma unroll
    for (int ks = 0; ks < 6; ks++) {
        uint32_t bf[4][2];
        #pragma unroll
        for (int nt = 0; nt < 4; nt++) {
            bf[nt][0] = *(const uint32_t*)&sB2[(nt * 8 + g) * ASTR + kB[ks] + 2 * t4];
            bf[nt][1] = *(const uint32_t*)&sB2[(nt * 8 + g) * ASTR + kB[ks] + 2 * t4 + 8];
        }
        #pragma unroll
        for (int mt = 0; mt < 2; mt++) {
            int r0 = w * 32 + mt * 16 + g;
            uint32_t af[4];
            af[0] = *(const uint32_t*)&sA[r0       * ASTR + kA[ks] + 2 * t4];
            af[1] = *(const uint32_t*)&sA[(r0 + 8) * ASTR + kA[ks] + 2 * t4];
            af[2] = *(const uint32_t*)&sA[r0       * ASTR + kA[ks] + 2 * t4 + 8];
            af[3] = *(const uint32_t*)&sA[(r0 + 8) * ASTR + kA[ks] + 2 * t4 + 8];
            #pragma unroll
            for (int nt = 0; nt < 4; nt++) mma16816(acc[mt][nt], af, bf[nt]);
        }
    }

    // ---- epilogue: row sum-of-squares (4-lane bfly), normalize, store ----
    #pragma unroll
    for (int mt = 0; mt < 2; mt++) {
        int r0 = w * 32 + mt * 16 + g;
        float s0 = 0.0f, s1 = 0.0f;
        #pragma unroll
        for (int nt = 0; nt < 4; nt++) {
            s0 = fmaf(acc[mt][nt][0], acc[mt][nt][0], s0);
            s0 = fmaf(acc[mt][nt][1], acc[mt][nt][1], s0);
            s1 = fmaf(acc[mt][nt][2], acc[mt][nt][2], s1);
            s1 = fmaf(acc[mt][nt][3], acc[mt][nt][3], s1);
        }
        s0 += __shfl_xor_sync(0xffffffffu, s0, 1);
        s0 += __shfl_xor_sync(0xffffffffu, s0, 2);
        s1 += __shfl_xor_sync(0xffffffffu, s1, 1);
        s1 += __shfl_xor_sync(0xffffffffu, s1, 2);
        float inv0 = 1.0f / fmaxf(sqrtf(s0), 1e-12f);
        float inv1 = 1.0f / fmaxf(sqrtf(s1), 1e-12f);

        int tok0 = sTok[r0];
        int tok1 = sTok[r0 + 8];
        #pragma unroll
        for (int nt = 0; nt < 4; nt++) {
            int c = nt * 8 + 2 * t4;
            if (tok0 >= 0) {
                float2 v2 = make_float2(acc[mt][nt][0] * inv0, acc[mt][nt][1] * inv0);
                *(float2*)(out + (size_t)tok0 * DIM + c) = v2;
            }
            if (tok1 >= 0) {
                float2 v2 = make_float2(acc[mt][nt][2] * inv1, acc[mt][nt][3] * inv1);
                *(float2*)(out + (size_t)tok1 * DIM + c) = v2;
            }
        }
    }
}

// ---------------- launch -------------------------------------------------
extern "C" void kernel_launch(void* const* d_in, const int* in_sizes, int n_in,
                              void* d_out, int out_size) {
    const float* x  = (const float*)d_in[0];
    const float* W1 = (const float*)d_in[1];
    const float* b1 = (const float*)d_in[2];
    const float* W0 = (const float*)d_in[3];
    const float* b0 = (const float*)d_in[4];
    const void*  pos = d_in[5];
    float* out = (float*)d_out;

    int B = in_sizes[0] / DIM;
    if (B > MAXB) B = MAXB;
    int nblk_b = (B + TPB_B - 1) / TPB_B;
    int nblk_c = (B + TILE - 1) / TILE + N_EXPERTS - 1;

    void* cnt_ptr = nullptr;
    cudaGetSymbolAddress(&cnt_ptr, g_cnt);
    cudaMemsetAsync(cnt_ptr, 0, N_EXPERTS * sizeof(int), 0);

    k_bucket<<<nblk_b, TPB_B>>>(pos, B);
    k_compute<<<nblk_c, CTPB>>>(x, W1, b1, W0, b0, out);
}

// round 11
// speedup vs baseline: 1.2213x; 1.1099x over previous
#include <cuda_runtime.h>
#include <cuda_bf16.h>
#include <stdint.h>

#define N_EXPERTS 20
#define DIM 32
#define MAXB (1 << 17)     // 131072
#define TPB_B 256
#define TILE 128           // tokens per compute CTA
#define CTPB 128
#define ASTR 72            // tile row stride in bf16 elems (144B, conflict-free)

__device__ int g_cnt[N_EXPERTS];
__device__ int g_bucket[N_EXPERTS * MAXB];

// ---- kernel 1: fused bucket (warp-aggregated hist + claim + write) ------
__global__ void __launch_bounds__(TPB_B) k_bucket(const void* __restrict__ pos, int B) {
    __shared__ int sh[N_EXPERTS];
    __shared__ int sbase[N_EXPERTS];
    __shared__ int s_is64;

    if (threadIdx.x < N_EXPERTS) sh[threadIdx.x] = 0;
    if (threadIdx.x < 32) {
        // int64 pos => all odd 32-bit words are zero high-words (values < 20)
        int v = ((const int*)pos)[2 * threadIdx.x + 1];   // B >= 64 guaranteed
        unsigned nz = __ballot_sync(0xffffffffu, v != 0);
        if (threadIdx.x == 0) s_is64 = (nz == 0) ? 1 : 0;
    }
    __syncthreads();

    int t = blockIdx.x * TPB_B + threadIdx.x;
    bool valid = (t < B);
    int e = valid
          ? (s_is64 ? (int)((const long long*)pos)[t] : ((const int*)pos)[t])
          : -1;

    unsigned mm = __match_any_sync(0xffffffffu, e);
    int lane = threadIdx.x & 31;
    int rank = __popc(mm & ((1u << lane) - 1));
    int leader = __ffs(mm) - 1;
    int wbase = 0;
    if (lane == leader && valid) wbase = atomicAdd(&sh[e], __popc(mm));
    wbase = __shfl_sync(0xffffffffu, wbase, leader);
    int r = wbase + rank;

    __syncthreads();
    if (threadIdx.x < N_EXPERTS) {
        int c = sh[threadIdx.x];
        sbase[threadIdx.x] = c ? atomicAdd(&g_cnt[threadIdx.x], c) : 0;
    }
    __syncthreads();
    if (valid) g_bucket[e * MAXB + sbase[e] + r] = t;
}

// ---- mma.sync wrapper ----------------------------------------------------
__device__ __forceinline__ void mma16816(float* c, const uint32_t* a, const uint32_t* b) {
    asm volatile(
        "mma.sync.aligned.m16n8k16.row.col.f32.bf16.bf16.f32 "
        "{%0,%1,%2,%3}, {%4,%5,%6,%7}, {%8,%9}, {%0,%1,%2,%3};"
        : "+f"(c[0]), "+f"(c[1]), "+f"(c[2]), "+f"(c[3])
        : "r"(a[0]), "r"(a[1]), "r"(a[2]), "r"(a[3]), "r"(b[0]), "r"(b[1]));
}

// split one fp32 pair into hi/lo bf16
__device__ __forceinline__ void split2(float a, float b, uint32_t& hi, uint32_t& lo) {
    __nv_bfloat162 hp = __floats2bfloat162_rn(a, b);
    float ra = a - __bfloat162float(hp.x);
    float rb = b - __bfloat162float(hp.y);
    __nv_bfloat162 lp = __floats2bfloat162_rn(ra, rb);
    hi = *reinterpret_cast<uint32_t*>(&hp);
    lo = *reinterpret_cast<uint32_t*>(&lp);
}

// ---- kernel 2: HMMA compute ---------------------------------------------
// MLP prologue (weights LDG first, gather overlaps) + quad-cooperative x
// gather: each 4-lane quad fetches 4 token rows, lane t4 loading bytes
// [32*t4, 32*t4+32) of each row -> 8 distinct 128B lines per LDG instr
// instead of 32 (4x fewer L1 wavefronts). One block barrier total.
__global__ void __launch_bounds__(CTPB) k_compute(
    const float* __restrict__ x,
    const float* __restrict__ W1, const float* __restrict__ b1,
    const float* __restrict__ W0, const float* __restrict__ b0,
    float* __restrict__ out)
{
    __shared__ __align__(16) __nv_bfloat16 sA[TILE * ASTR];      // 18432 B
    __shared__ __align__(16) __nv_bfloat16 sB1[DIM * ASTR];      // 4608 B
    __shared__ __align__(16) __nv_bfloat16 sB2[DIM * ASTR];      // 4608 B
    __shared__ __align__(16) float sb1[DIM], sb0[DIM];
    __shared__ int sTok[TILE];

    int tid = threadIdx.x;
    int l   = tid & 31;

    // ---- block -> (expert, tile): parallel load + warp scan ----
    int rem = blockIdx.x;
    int cnt = (l < N_EXPERTS) ? g_cnt[l] : 0;          // one broadcast LDG
    int nb  = (cnt + TILE - 1) / TILE;
    int s = nb;
    #pragma unroll
    for (int d = 1; d < 32; d <<= 1) {
        int u = __shfl_up_sync(0xffffffffu, s, d);
        if (l >= d) s += u;
    }
    int excl = s - nb;
    bool hit = (l < N_EXPERTS) && (rem >= excl) && (rem < excl + nb);
    unsigned hm = __ballot_sync(0xffffffffu, hit);
    if (hm == 0) return;                                // beyond total work (uniform)
    int el  = __ffs(hm) - 1;
    int e   = el;
    int n   = __shfl_sync(0xffffffffu, cnt, el);
    int base = (rem - __shfl_sync(0xffffffffu, excl, el)) * TILE;

    // ---- phase 1: issue ALL independent LDGs (weights), then gather ----
    float w1r[8], w0r[8];
    #pragma unroll
    for (int q = 0; q < 8; q++) {
        int i = tid + q * CTPB;
        w1r[q] = W1[e * DIM * DIM + i];
        w0r[q] = W0[e * DIM * DIM + i];
    }
    float bv1 = 0.0f, bv0 = 0.0f;
    if (tid < DIM) {
        bv1 = b1[e * DIM + tid];
        bv0 = b0[e * DIM + tid];
    }
    int slot = base + tid;
    int tok = (slot < n) ? g_bucket[e * MAXB + slot] : -1;   // coalesced

    // quad-cooperative gather: quad (lanes l4..l4+3) owns warp rows l4..l4+3
    int t4 = l & 3;
    int l4 = l & ~3;
    int tj[4];
    #pragma unroll
    for (int j = 0; j < 4; j++)
        tj[j] = __shfl_sync(0xffffffffu, tok, l4 + j);
    float v[4][8];
    #pragma unroll
    for (int j = 0; j < 4; j++) {
        #pragma unroll
        for (int k = 0; k < 8; k++) v[j][k] = 0.0f;
        if (tj[j] >= 0) {
            const float4* xp = (const float4*)(x + (size_t)tj[j] * DIM + t4 * 8);
            float4 a = xp[0];
            float4 b2 = xp[1];
            v[j][0] = a.x;  v[j][1] = a.y;  v[j][2] = a.z;  v[j][3] = a.w;
            v[j][4] = b2.x; v[j][5] = b2.y; v[j][6] = b2.z; v[j][7] = b2.w;
        }
    }

    // ---- phase 2: convert + STS (operands have landed) ----
    #pragma unroll
    for (int q = 0; q < 8; q++) {
        int i = tid + q * CTPB;
        int o = i >> 5, k = i & 31;
        __nv_bfloat16 h1 = __float2bfloat16(w1r[q]);
        sB1[o * ASTR + k]      = h1;
        sB1[o * ASTR + 32 + k] = __float2bfloat16(w1r[q] - __bfloat162float(h1));
        __nv_bfloat16 h0 = __float2bfloat16(w0r[q]);
        sB2[o * ASTR + k]      = h0;
        sB2[o * ASTR + 32 + k] = __float2bfloat16(w0r[q] - __bfloat162float(h0));
    }
    if (tid < DIM) {
        sb1[tid] = bv1;
        sb0[tid] = bv0;
    }
    sTok[tid] = tok;
    #pragma unroll
    for (int j = 0; j < 4; j++) {
        int R = (tid & ~31) + l4 + j;     // tile row
        uint32_t hi[4], lo[4];
        split2(v[j][0], v[j][1], hi[0], lo[0]);
        split2(v[j][2], v[j][3], hi[1], lo[1]);
        split2(v[j][4], v[j][5], hi[2], lo[2]);
        split2(v[j][6], v[j][7], hi[3], lo[3]);
        *(uint4*)&sA[R * ASTR + 8 * t4]      = make_uint4(hi[0], hi[1], hi[2], hi[3]);
        *(uint4*)&sA[R * ASTR + 32 + 8 * t4] = make_uint4(lo[0], lo[1], lo[2], lo[3]);
    }
    __syncthreads();   // the ONLY block barrier: publishes sB1/sB2/biases (+A)

    // ---- fragment geometry ----
    int w  = tid >> 5;
    int g  = l >> 2;           // 0..7
    const int kA[6] = {0, 16, 32, 48, 0, 16};
    const int kB[6] = {0, 16, 0, 16, 32, 48};

    float acc[2][4][4];

    // ======================= layer 1 =======================
    #pragma unroll
    for (int mt = 0; mt < 2; mt++)
        #pragma unroll
        for (int nt = 0; nt < 4; nt++) {
            float2 bv = *(const float2*)&sb1[nt * 8 + 2 * t4];
            acc[mt][nt][0] = bv.x; acc[mt][nt][1] = bv.y;
            acc[mt][nt][2] = bv.x; acc[mt][nt][3] = bv.y;
        }
    #pragma unroll
    for (int ks = 0; ks < 6; ks++) {
        uint32_t bf[4][2];
        #pragma unroll
        for (int nt = 0; nt < 4; nt++) {
            bf[nt][0] = *(const uint32_t*)&sB1[(nt * 8 + g) * ASTR + kB[ks] + 2 * t4];
            bf[nt][1] = *(const uint32_t*)&sB1[(nt * 8 + g) * ASTR + kB[ks] + 2 * t4 + 8];
        }
        #pragma unroll
        for (int mt = 0; mt < 2; mt++) {
            int r0 = w * 32 + mt * 16 + g;
            uint32_t af[4];
            af[0] = *(const uint32_t*)&sA[r0       * ASTR + kA[ks] + 2 * t4];
            af[1] = *(const uint32_t*)&sA[(r0 + 8) * ASTR + kA[ks] + 2 * t4];
            af[2] = *(const uint32_t*)&sA[r0       * ASTR + kA[ks] + 2 * t4 + 8];
            af[3] = *(const uint32_t*)&sA[(r0 + 8) * ASTR + kA[ks] + 2 * t4 + 8];
            #pragma unroll
            for (int nt = 0; nt < 4; nt++) mma16816(acc[mt][nt], af, bf[nt]);
        }
    }

    // write h back into A tile (hi/lo) — warp-local rows only
    #pragma unroll
    for (int mt = 0; mt < 2; mt++) {
        int r0 = w * 32 + mt * 16 + g;
        #pragma unroll
        for (int nt = 0; nt < 4; nt++) {
            int c = nt * 8 + 2 * t4;
            uint32_t hi0, lo0, hi1, lo1;
            split2(acc[mt][nt][0], acc[mt][nt][1], hi0, lo0);
            split2(acc[mt][nt][2], acc[mt][nt][3], hi1, lo1);
            *(uint32_t*)&sA[r0 * ASTR + c]            = hi0;
            *(uint32_t*)&sA[r0 * ASTR + 32 + c]       = lo0;
            *(uint32_t*)&sA[(r0 + 8) * ASTR + c]      = hi1;
            *(uint32_t*)&sA[(r0 + 8) * ASTR + 32 + c] = lo1;
        }
    }
    __syncwarp();

    // ======================= layer 0 =======================
    #pragma unroll
    for (int mt = 0; mt < 2; mt++)
        #pragma unroll
        for (int nt = 0; nt < 4; nt++) {
            float2 bv = *(const float2*)&sb0[nt * 8 + 2 * t4];
            acc[mt][nt][0] = bv.x; acc[mt][nt][1] = bv.y;
            acc[mt][nt][2] = bv.x; acc[mt][nt][3] = bv.y;
        }
    #pragma unroll
    for (int ks = 0; ks < 6; ks++) {
        uint32_t bf[4][2];
        #pragma unroll
        for (int nt = 0; nt < 4; nt++) {
            bf[nt][0] = *(const uint32_t*)&sB2[(nt * 8 + g) * ASTR + kB[ks] + 2 * t4];
            bf[nt][1] = *(const uint32_t*)&sB2[(nt * 8 + g) * ASTR + kB[ks] + 2 * t4 + 8];
        }
        #pragma unroll
        for (int mt = 0; mt < 2; mt++) {
            int r0 = w * 32 + mt * 16 + g;
            uint32_t af[4];
            af[0] = *(const uint32_t*)&sA[r0       * ASTR + kA[ks] + 2 * t4];
            af[1] = *(const uint32_t*)&sA[(r0 + 8) * ASTR + kA[ks] + 2 * t4];
            af[2] = *(const uint32_t*)&sA[r0       * ASTR + kA[ks] + 2 * t4 + 8];
            af[3] = *(const uint32_t*)&sA[(r0 + 8) * ASTR + kA[ks] + 2 * t4 + 8];
            #pragma unroll
            for (int nt = 0; nt < 4; nt++) mma16816(acc[mt][nt], af, bf[nt]);
        }
    }

    // ---- epilogue: row sum-of-squares (4-lane bfly), normalize, store ----
    #pragma unroll
    for (int mt = 0; mt < 2; mt++) {
        int r0 = w * 32 + mt * 16 + g;
        float s0 = 0.0f, s1 = 0.0f;
        #pragma unroll
        for (int nt = 0; nt < 4; nt++) {
            s0 = fmaf(acc[mt][nt][0], acc[mt][nt][0], s0);
            s0 = fmaf(acc[mt][nt][1], acc[mt][nt][1], s0);
            s1 = fmaf(acc[mt][nt][2], acc[mt][nt][2], s1);
            s1 = fmaf(acc[mt][nt][3], acc[mt][nt][3], s1);
        }
        s0 += __shfl_xor_sync(0xffffffffu, s0, 1);
        s0 += __shfl_xor_sync(0xffffffffu, s0, 2);
        s1 += __shfl_xor_sync(0xffffffffu, s1, 1);
        s1 += __shfl_xor_sync(0xffffffffu, s1, 2);
        float inv0 = 1.0f / fmaxf(sqrtf(s0), 1e-12f);
        float inv1 = 1.0f / fmaxf(sqrtf(s1), 1e-12f);

        int tok0 = sTok[r0];
        int tok1 = sTok[r0 + 8];
        #pragma unroll
        for (int nt = 0; nt < 4; nt++) {
            int c = nt * 8 + 2 * t4;
            if (tok0 >= 0) {
                float2 v2 = make_float2(acc[mt][nt][0] * inv0, acc[mt][nt][1] * inv0);
                *(float2*)(out + (size_t)tok0 * DIM + c) = v2;
            }
            if (tok1 >= 0) {
                float2 v2 = make_float2(acc[mt][nt][2] * inv1, acc[mt][nt][3] * inv1);
                *(float2*)(out + (size_t)tok1 * DIM + c) = v2;
            }
        }
    }
}

// ---------------- launch -------------------------------------------------
extern "C" void kernel_launch(void* const* d_in, const int* in_sizes, int n_in,
                              void* d_out, int out_size) {
    const float* x  = (const float*)d_in[0];
    const float* W1 = (const float*)d_in[1];
    const float* b1 = (const float*)d_in[2];
    const float* W0 = (const float*)d_in[3];
    const float* b0 = (const float*)d_in[4];
    const void*  pos = d_in[5];
    float* out = (float*)d_out;

    int B = in_sizes[0] / DIM;
    if (B > MAXB) B = MAXB;
    int nblk_b = (B + TPB_B - 1) / TPB_B;
    int nblk_c = (B + TILE - 1) / TILE + N_EXPERTS - 1;

    void* cnt_ptr = nullptr;
    cudaGetSymbolAddress(&cnt_ptr, g_cnt);
    cudaMemsetAsync(cnt_ptr, 0, N_EXPERTS * sizeof(int), 0);

    k_bucket<<<nblk_b, TPB_B>>>(pos, B);
    k_compute<<<nblk_c, CTPB>>>(x, W1, b1, W0, b0, out);
}